// round 1
// baseline (speedup 1.0000x reference)
#include <cuda_runtime.h>
#include <math.h>
#include <float.h>

#define Bb 4
#define Nn 8192
#define Ss 2048
#define Kk 64
#define EPSf 1e-5f

// ---------------- scratch (no allocations allowed) ----------------
__device__ int   g_idx_fps[Bb*Ss];
__device__ float g_cen[Bb*Ss*3];
__device__ int   g_idx_ball[Bb*Ss*Kk];
__device__ float g_wf1[64*67];
__device__ float g_bf1[64];
__device__ float g_wf2[64*64];
__device__ float g_bf2[64];
__device__ float g_wf3[128*64];
__device__ float g_bf3[128];

// ---------------- fold BN into conv ----------------
__global__ void fold_kernel(
    const float* W1, const float* b1, const float* g1, const float* bt1, const float* m1, const float* v1,
    const float* W2, const float* b2, const float* g2, const float* bt2, const float* m2, const float* v2,
    const float* W3, const float* b3, const float* g3, const float* bt3, const float* m3, const float* v3)
{
    int t = threadIdx.x;
    for (int i = t; i < 64*67; i += blockDim.x) {
        int o = i / 67;
        g_wf1[i] = W1[i] * (g1[o] * rsqrtf(v1[o] + EPSf));
    }
    for (int i = t; i < 64; i += blockDim.x)
        g_bf1[i] = (b1[i] - m1[i]) * (g1[i] * rsqrtf(v1[i] + EPSf)) + bt1[i];

    for (int i = t; i < 64*64; i += blockDim.x) {
        int o = i >> 6;
        g_wf2[i] = W2[i] * (g2[o] * rsqrtf(v2[o] + EPSf));
    }
    for (int i = t; i < 64; i += blockDim.x)
        g_bf2[i] = (b2[i] - m2[i]) * (g2[i] * rsqrtf(v2[i] + EPSf)) + bt2[i];

    for (int i = t; i < 128*64; i += blockDim.x) {
        int o = i >> 6;
        g_wf3[i] = W3[i] * (g3[o] * rsqrtf(v3[o] + EPSf));
    }
    for (int i = t; i < 128; i += blockDim.x)
        g_bf3[i] = (b3[i] - m3[i]) * (g3[i] * rsqrtf(v3[i] + EPSf)) + bt3[i];
}

// ---------------- farthest point sampling ----------------
// One block per batch; 1024 threads; 8 points per thread held in registers.
// Distance math mirrors XLA exactly: rn-mul / rn-add, association (dx2+dy2)+dz2,
// argmax ties -> lowest index (first occurrence, like jnp.argmax).
__global__ void __launch_bounds__(1024) fps_kernel(const float* __restrict__ x,
                                                   float* __restrict__ out)
{
    const int b = blockIdx.x;
    const int t = threadIdx.x;
    const int PPT = Nn / 1024;  // 8
    const float* xb = x + (size_t)b * Nn * 3;

    float px[8], py[8], pz[8], dist[8];
#pragma unroll
    for (int j = 0; j < PPT; j++) {
        int p = t * PPT + j;
        px[j] = xb[p*3 + 0];
        py[j] = xb[p*3 + 1];
        pz[j] = xb[p*3 + 2];
        dist[j] = 1e10f;
    }

    __shared__ float s_c[3];
    __shared__ float s_val[32];
    __shared__ int   s_idx[32];
    __shared__ int   s_cur;

    int cur = 0;
    for (int s = 0; s < Ss; s++) {
        // owner of current farthest publishes its coordinates
        if (cur >= t*PPT && cur < t*PPT + PPT) {
            int j = cur - t*PPT;
            s_c[0] = px[j]; s_c[1] = py[j]; s_c[2] = pz[j];
        }
        if (t == 0) g_idx_fps[b*Ss + s] = cur;
        __syncthreads();

        float cx = s_c[0], cy = s_c[1], cz = s_c[2];
        if (t == 0) {
            int oc = (b*Ss + s) * 3;
            g_cen[oc+0] = cx; g_cen[oc+1] = cy; g_cen[oc+2] = cz;
            out[oc+0] = cx;   out[oc+1] = cy;   out[oc+2] = cz;
        }

        float bestv = -1.0f;
        int   besti = Nn;
#pragma unroll
        for (int j = 0; j < PPT; j++) {
            float dx = __fsub_rn(px[j], cx);
            float dy = __fsub_rn(py[j], cy);
            float dz = __fsub_rn(pz[j], cz);
            float d  = __fadd_rn(__fadd_rn(__fmul_rn(dx,dx), __fmul_rn(dy,dy)),
                                 __fmul_rn(dz,dz));
            float nd = fminf(dist[j], d);
            dist[j] = nd;
            if (nd > bestv) { bestv = nd; besti = t*PPT + j; }  // strict > keeps lowest index
        }
        // warp argmax (value desc, index asc on ties)
#pragma unroll
        for (int off = 16; off; off >>= 1) {
            float ov = __shfl_down_sync(0xffffffffu, bestv, off);
            int   oi = __shfl_down_sync(0xffffffffu, besti, off);
            if (ov > bestv || (ov == bestv && oi < besti)) { bestv = ov; besti = oi; }
        }
        if ((t & 31) == 0) { s_val[t >> 5] = bestv; s_idx[t >> 5] = besti; }
        __syncthreads();
        if (t < 32) {
            bestv = s_val[t]; besti = s_idx[t];
#pragma unroll
            for (int off = 16; off; off >>= 1) {
                float ov = __shfl_down_sync(0xffffffffu, bestv, off);
                int   oi = __shfl_down_sync(0xffffffffu, besti, off);
                if (ov > bestv || (ov == bestv && oi < besti)) { bestv = ov; besti = oi; }
            }
            if (t == 0) s_cur = besti;
        }
        __syncthreads();
        cur = s_cur;
    }
}

// ---------------- ball query: first K=64 indices (ascending) within radius ----------------
// One warp per centroid; 8 warps per block. Warp-ballot preserves index order.
// Threshold: f32(0.04) — what JAX's weak-typed python-float promotion compares against.
__global__ void __launch_bounds__(256) ball_kernel(const float* __restrict__ x)
{
    int cen  = blockIdx.x * 8 + (threadIdx.x >> 5);
    int lane = threadIdx.x & 31;
    if (cen >= Bb * Ss) return;
    int b = cen >> 11;  // / Ss (2048)

    float cx = g_cen[cen*3 + 0];
    float cy = g_cen[cen*3 + 1];
    float cz = g_cen[cen*3 + 2];
    const float* xb = x + (size_t)b * Nn * 3;
    int* outp = g_idx_ball + (size_t)cen * Kk;

    int count = 0;
    for (int base = 0; base < Nn && count < Kk; base += 32) {
        int p = base + lane;
        float qx = xb[p*3 + 0], qy = xb[p*3 + 1], qz = xb[p*3 + 2];
        float dx = __fsub_rn(cx, qx);
        float dy = __fsub_rn(cy, qy);
        float dz = __fsub_rn(cz, qz);
        float d  = __fadd_rn(__fadd_rn(__fmul_rn(dx,dx), __fmul_rn(dy,dy)),
                             __fmul_rn(dz,dz));
        bool hit = d < 0.04f;
        unsigned m = __ballot_sync(0xffffffffu, hit);
        int rank = __popc(m & ((1u << lane) - 1u));
        if (hit && (count + rank) < Kk) outp[count + rank] = p;
        count += __popc(m);
    }
    count = min(count, Kk);
    for (int q = count + lane; q < Kk; q += 32) outp[q] = -1;
}

// ---------------- fused gather + MLP(67->64->64->128) + masked maxpool ----------------
#define MLP_THREADS 128
#define CPG 4
// shared layout (float offsets)
#define OW1 0
#define OB1 (OW1 + 64*67)
#define OW2 (OB1 + 64)
#define OB2 (OW2 + 64*65)
#define OW3 (OB2 + 64)
#define OB3 (OW3 + 128*65)
#define OF  (OB3 + 128)          // F [67][65], reused as H2 [64][65]
#define OH  (OF  + 67*65)        // H1 [64][65]
#define OIDX (OH + 64*65)        // 64 ints
#define OCEN (OIDX + 64)
#define SMEM_FLOATS (OCEN + 3)
#define SMEM_BYTES  (SMEM_FLOATS * 4)

__global__ void __launch_bounds__(MLP_THREADS, 2)
mlp_kernel(const float* __restrict__ x, const float* __restrict__ xc,
           float* __restrict__ out)
{
    extern __shared__ float sm[];
    const int tid  = threadIdx.x;
    const int tx   = tid & 15;   // k-tile selector (4 cols each)
    const int ty   = tid >> 4;   // o-tile selector (8 rows each)
    const int lane = tid & 31;
    const int warp = tid >> 5;

    // stage folded weights once per block
    for (int i = tid; i < 64*67; i += MLP_THREADS) sm[OW1 + i] = g_wf1[i];
    for (int i = tid; i < 64*64; i += MLP_THREADS) {
        int o = i >> 6, c = i & 63;
        sm[OW2 + o*65 + c] = g_wf2[i];
    }
    for (int i = tid; i < 128*64; i += MLP_THREADS) {
        int o = i >> 6, c = i & 63;
        sm[OW3 + o*65 + c] = g_wf3[i];
    }
    for (int i = tid; i < 64;  i += MLP_THREADS) { sm[OB1+i] = g_bf1[i]; sm[OB2+i] = g_bf2[i]; }
    for (int i = tid; i < 128; i += MLP_THREADS) sm[OB3 + i] = g_bf3[i];

    int* sidx = (int*)&sm[OIDX];
    float* pooled = out + (size_t)Bb * Ss * 3;

    for (int g = 0; g < CPG; g++) {
        const int cen = blockIdx.x * CPG + g;
        const int b = cen >> 11;
        __syncthreads();  // buffers from previous iter (and weight staging) done

        if (tid < Kk) sidx[tid] = g_idx_ball[(size_t)cen * Kk + tid];
        if (tid < 3)  sm[OCEN + tid] = g_cen[cen*3 + tid];
        __syncthreads();

        // ---- gather: F[c][k], c:0..63 = x_complete channels, 64..66 = rel coords
        const float* xcb = xc + (size_t)b * Nn * 64;
        const float* xb  = x  + (size_t)b * Nn * 3;
        for (int kk = 0; kk < 16; kk++) {
            int k  = warp * 16 + kk;
            int gi = sidx[k];
            gi = gi < 0 ? 0 : gi;
            const float* row = xcb + (size_t)gi * 64;
            sm[OF + lane*65 + k]      = row[lane];
            sm[OF + (lane+32)*65 + k] = row[lane + 32];
            if (lane < 3)
                sm[OF + (64+lane)*65 + k] = xb[gi*3 + lane] - sm[OCEN + lane];
        }
        __syncthreads();

        float acc[8][4];

        // ---- layer 1: H1[64][64] = relu(W1f @ F + b1f)
#pragma unroll
        for (int i = 0; i < 8; i++)
#pragma unroll
            for (int j = 0; j < 4; j++) acc[i][j] = 0.f;
        for (int c = 0; c < 67; c++) {
            float fv[4];
#pragma unroll
            for (int j = 0; j < 4; j++) fv[j] = sm[OF + c*65 + tx*4 + j];
#pragma unroll
            for (int i = 0; i < 8; i++) {
                float wv = sm[OW1 + (ty*8 + i)*67 + c];
#pragma unroll
                for (int j = 0; j < 4; j++) acc[i][j] = fmaf(wv, fv[j], acc[i][j]);
            }
        }
#pragma unroll
        for (int i = 0; i < 8; i++) {
            float bia = sm[OB1 + ty*8 + i];
#pragma unroll
            for (int j = 0; j < 4; j++)
                sm[OH + (ty*8 + i)*65 + tx*4 + j] = fmaxf(acc[i][j] + bia, 0.f);
        }
        __syncthreads();

        // ---- layer 2: H2[64][64] = relu(W2f @ H1 + b2f), written into F buffer
#pragma unroll
        for (int i = 0; i < 8; i++)
#pragma unroll
            for (int j = 0; j < 4; j++) acc[i][j] = 0.f;
        for (int c = 0; c < 64; c++) {
            float fv[4];
#pragma unroll
            for (int j = 0; j < 4; j++) fv[j] = sm[OH + c*65 + tx*4 + j];
#pragma unroll
            for (int i = 0; i < 8; i++) {
                float wv = sm[OW2 + (ty*8 + i)*65 + c];
#pragma unroll
                for (int j = 0; j < 4; j++) acc[i][j] = fmaf(wv, fv[j], acc[i][j]);
            }
        }
#pragma unroll
        for (int i = 0; i < 8; i++) {
            float bia = sm[OB2 + ty*8 + i];
#pragma unroll
            for (int j = 0; j < 4; j++)
                sm[OF + (ty*8 + i)*65 + tx*4 + j] = fmaxf(acc[i][j] + bia, 0.f);
        }
        __syncthreads();

        // ---- layer 3 (128 outs, two 64-row passes) fused with masked maxpool
        for (int op = 0; op < 2; op++) {
#pragma unroll
            for (int i = 0; i < 8; i++)
#pragma unroll
                for (int j = 0; j < 4; j++) acc[i][j] = 0.f;
            for (int c = 0; c < 64; c++) {
                float fv[4];
#pragma unroll
                for (int j = 0; j < 4; j++) fv[j] = sm[OF + c*65 + tx*4 + j];
#pragma unroll
                for (int i = 0; i < 8; i++) {
                    float wv = sm[OW3 + (op*64 + ty*8 + i)*65 + c];
#pragma unroll
                    for (int j = 0; j < 4; j++) acc[i][j] = fmaf(wv, fv[j], acc[i][j]);
                }
            }
#pragma unroll
            for (int i = 0; i < 8; i++) {
                int o = op*64 + ty*8 + i;
                float bia = sm[OB3 + o];
                float m = -INFINITY;
#pragma unroll
                for (int j = 0; j < 4; j++) {
                    int k = tx*4 + j;
                    float v = fmaxf(acc[i][j] + bia, 0.f);
                    if (sidx[k] >= 0) m = fmaxf(m, v);
                }
                // reduce across the 16 tx threads (contiguous 16-lane groups)
#pragma unroll
                for (int off = 8; off; off >>= 1)
                    m = fmaxf(m, __shfl_xor_sync(0xffffffffu, m, off, 16));
                if (tx == 0) pooled[(size_t)cen * 128 + o] = m;
            }
        }
    }
}

// ---------------- launch ----------------
extern "C" void kernel_launch(void* const* d_in, const int* in_sizes, int n_in,
                              void* d_out, int out_size)
{
    const float* x   = (const float*)d_in[0];
    const float* xc  = (const float*)d_in[1];
    const float* W1  = (const float*)d_in[2];
    const float* b1  = (const float*)d_in[3];
    const float* g1  = (const float*)d_in[4];
    const float* bt1 = (const float*)d_in[5];
    const float* m1  = (const float*)d_in[6];
    const float* v1  = (const float*)d_in[7];
    const float* W2  = (const float*)d_in[8];
    const float* b2  = (const float*)d_in[9];
    const float* g2  = (const float*)d_in[10];
    const float* bt2 = (const float*)d_in[11];
    const float* m2  = (const float*)d_in[12];
    const float* v2  = (const float*)d_in[13];
    const float* W3  = (const float*)d_in[14];
    const float* b3  = (const float*)d_in[15];
    const float* g3  = (const float*)d_in[16];
    const float* bt3 = (const float*)d_in[17];
    const float* m3  = (const float*)d_in[18];
    const float* v3  = (const float*)d_in[19];
    float* out = (float*)d_out;

    fold_kernel<<<1, 256>>>(W1,b1,g1,bt1,m1,v1, W2,b2,g2,bt2,m2,v2, W3,b3,g3,bt3,m3,v3);
    fps_kernel<<<Bb, 1024>>>(x, out);
    ball_kernel<<<(Bb*Ss)/8, 256>>>(x);

    cudaFuncSetAttribute(mlp_kernel, cudaFuncAttributeMaxDynamicSharedMemorySize, SMEM_BYTES);
    mlp_kernel<<<(Bb*Ss)/CPG, MLP_THREADS, SMEM_BYTES>>>(x, xc, out);
}

// round 2
// speedup vs baseline: 1.3902x; 1.3902x over previous
#include <cuda_runtime.h>
#include <math.h>
#include <float.h>

#define Bb 4
#define Nn 8192
#define Ss 2048
#define Kk 64
#define EPSf 1e-5f

typedef unsigned long long ull;

// ---------------- scratch (no allocations allowed) ----------------
__device__ float g_cen[Bb*Ss*3];
__device__ int   g_idx_ball[Bb*Ss*Kk];
__device__ float g_wf1[64*67];
__device__ float g_bf1[64];
__device__ float g_wf2[64*64];
__device__ float g_bf2[64];
__device__ float g_wf3[128*64];
__device__ float g_bf3[128];

// ---------------- packed f32x2 helpers (per-lane rn == scalar rn) ----------------
__device__ __forceinline__ ull pk2(float lo, float hi) {
    ull r; asm("mov.b64 %0, {%1, %2};" : "=l"(r) : "f"(lo), "f"(hi)); return r;
}
__device__ __forceinline__ void up2(ull v, float& a, float& b) {
    asm("mov.b64 {%0, %1}, %2;" : "=f"(a), "=f"(b) : "l"(v));
}
__device__ __forceinline__ ull add2(ull a, ull b) {
    ull r; asm("add.rn.f32x2 %0, %1, %2;" : "=l"(r) : "l"(a), "l"(b)); return r;
}
__device__ __forceinline__ ull mul2(ull a, ull b) {
    ull r; asm("mul.rn.f32x2 %0, %1, %2;" : "=l"(r) : "l"(a), "l"(b)); return r;
}

// ---------------- fold BN into conv ----------------
__global__ void fold_kernel(
    const float* W1, const float* b1, const float* g1, const float* bt1, const float* m1, const float* v1,
    const float* W2, const float* b2, const float* g2, const float* bt2, const float* m2, const float* v2,
    const float* W3, const float* b3, const float* g3, const float* bt3, const float* m3, const float* v3)
{
    int t = threadIdx.x;
    for (int i = t; i < 64*67; i += blockDim.x) {
        int o = i / 67;
        g_wf1[i] = W1[i] * (g1[o] * rsqrtf(v1[o] + EPSf));
    }
    for (int i = t; i < 64; i += blockDim.x)
        g_bf1[i] = (b1[i] - m1[i]) * (g1[i] * rsqrtf(v1[i] + EPSf)) + bt1[i];

    for (int i = t; i < 64*64; i += blockDim.x) {
        int o = i >> 6;
        g_wf2[i] = W2[i] * (g2[o] * rsqrtf(v2[o] + EPSf));
    }
    for (int i = t; i < 64; i += blockDim.x)
        g_bf2[i] = (b2[i] - m2[i]) * (g2[i] * rsqrtf(v2[i] + EPSf)) + bt2[i];

    for (int i = t; i < 128*64; i += blockDim.x) {
        int o = i >> 6;
        g_wf3[i] = W3[i] * (g3[o] * rsqrtf(v3[o] + EPSf));
    }
    for (int i = t; i < 128; i += blockDim.x)
        g_bf3[i] = (b3[i] - m3[i]) * (g3[i] * rsqrtf(v3[i] + EPSf)) + bt3[i];
}

// ---------------- farthest point sampling ----------------
// One block per batch; 1024 threads; 8 points per thread in packed f32x2 regs.
// Distance math matches XLA exactly: rn mul/add, association (dx2+dy2)+dz2.
// Argmax tie-break = lowest index (first occurrence), enforced at thread,
// warp (redux max value + redux min matching index) and block levels.
__global__ void __launch_bounds__(1024, 1) fps_kernel(const float* __restrict__ x,
                                                      float* __restrict__ out)
{
    const int b = blockIdx.x;
    const int t = threadIdx.x;
    const float* xb = x + (size_t)b * Nn * 3;

    ull px[4], py[4], pz[4];
    float dist[8];
#pragma unroll
    for (int i = 0; i < 4; i++) {
        int p = t * 8 + i * 2;
        px[i] = pk2(xb[p*3 + 0], xb[p*3 + 3]);
        py[i] = pk2(xb[p*3 + 1], xb[p*3 + 4]);
        pz[i] = pk2(xb[p*3 + 2], xb[p*3 + 5]);
        dist[2*i] = 1e10f; dist[2*i+1] = 1e10f;
    }

    __shared__ float    s_c[3];
    __shared__ unsigned s_val[32];
    __shared__ unsigned s_idx[32];

    const int lane = t & 31;
    int cur = 0;

    for (int s = 0; s < Ss; s++) {
        // owner of current farthest publishes coords + writes outputs
        unsigned jj = (unsigned)(cur - t*8);
        if (jj < 8u) {
            float a0, a1, X, Y, Z;
            up2(px[jj>>1], a0, a1); X = (jj & 1) ? a1 : a0;
            up2(py[jj>>1], a0, a1); Y = (jj & 1) ? a1 : a0;
            up2(pz[jj>>1], a0, a1); Z = (jj & 1) ? a1 : a0;
            s_c[0] = X; s_c[1] = Y; s_c[2] = Z;
            int oc = (b*Ss + s) * 3;
            g_cen[oc+0] = X; g_cen[oc+1] = Y; g_cen[oc+2] = Z;
            out[oc+0]  = X; out[oc+1]  = Y; out[oc+2]  = Z;
        }
        __syncthreads();   // also protects s_val/s_idx reuse from prior iter

        const float cx = s_c[0], cy = s_c[1], cz = s_c[2];
        const ull ncx = pk2(-cx, -cx);
        const ull ncy = pk2(-cy, -cy);
        const ull ncz = pk2(-cz, -cz);

        float mm[4];
#pragma unroll
        for (int i = 0; i < 4; i++) {
            ull dx = add2(px[i], ncx);
            ull dy = add2(py[i], ncy);
            ull dz = add2(pz[i], ncz);
            ull dd = add2(add2(mul2(dx,dx), mul2(dy,dy)), mul2(dz,dz));
            float d0, d1; up2(dd, d0, d1);
            float n0 = fminf(dist[2*i],   d0);
            float n1 = fminf(dist[2*i+1], d1);
            dist[2*i] = n0; dist[2*i+1] = n1;
            mm[i] = fmaxf(n0, n1);
        }
        float bestv = fmaxf(fmaxf(mm[0], mm[1]), fmaxf(mm[2], mm[3]));

        // warp argmax: max value (float-as-uint, all >=0), then min matching index
        unsigned mv   = __float_as_uint(bestv);
        unsigned wmax = __reduce_max_sync(0xffffffffu, mv);
        unsigned loc  = 0xffffffffu;
        if (mv == wmax) {
            float fm = __uint_as_float(wmax);
#pragma unroll
            for (int j = 7; j >= 0; j--)
                if (dist[j] == fm) loc = (unsigned)(t*8 + j);   // ends at smallest j
        }
        unsigned widx = __reduce_min_sync(0xffffffffu, loc);

        if (lane == 0) { s_val[t>>5] = wmax; s_idx[t>>5] = widx; }
        __syncthreads();

        // every warp redundantly reduces across the 32 warp results -> no 3rd barrier
        unsigned v  = s_val[lane];
        unsigned id = s_idx[lane];
        unsigned M  = __reduce_max_sync(0xffffffffu, v);
        unsigned cn = (v == M) ? id : 0xffffffffu;
        cur = (int)__reduce_min_sync(0xffffffffu, cn);
    }
}

// ---------------- ball query: first K=64 indices (ascending) within radius ----------------
__global__ void __launch_bounds__(256) ball_kernel(const float* __restrict__ x)
{
    int cen  = blockIdx.x * 8 + (threadIdx.x >> 5);
    int lane = threadIdx.x & 31;
    if (cen >= Bb * Ss) return;
    int b = cen >> 11;

    float cx = g_cen[cen*3 + 0];
    float cy = g_cen[cen*3 + 1];
    float cz = g_cen[cen*3 + 2];
    const float* xb = x + (size_t)b * Nn * 3;
    int* outp = g_idx_ball + (size_t)cen * Kk;

    int count = 0;
    for (int base = 0; base < Nn && count < Kk; base += 32) {
        int p = base + lane;
        float qx = xb[p*3 + 0], qy = xb[p*3 + 1], qz = xb[p*3 + 2];
        float dx = __fsub_rn(cx, qx);
        float dy = __fsub_rn(cy, qy);
        float dz = __fsub_rn(cz, qz);
        float d  = __fadd_rn(__fadd_rn(__fmul_rn(dx,dx), __fmul_rn(dy,dy)),
                             __fmul_rn(dz,dz));
        bool hit = d < 0.04f;
        unsigned m = __ballot_sync(0xffffffffu, hit);
        int rank = __popc(m & ((1u << lane) - 1u));
        if (hit && (count + rank) < Kk) outp[count + rank] = p;
        count += __popc(m);
    }
    count = min(count, Kk);
    for (int q = count + lane; q < Kk; q += 32) outp[q] = -1;
}

// ---------------- fused gather + MLP(67->64->64->128) + masked maxpool ----------------
#define MLP_THREADS 128
#define CPG 4
#define OW1 0
#define OB1 (OW1 + 64*67)
#define OW2 (OB1 + 64)
#define OB2 (OW2 + 64*65)
#define OW3 (OB2 + 64)
#define OB3 (OW3 + 128*65)
#define OF  (OB3 + 128)
#define OH  (OF  + 67*65)
#define OIDX (OH + 64*65)
#define OCEN (OIDX + 64)
#define SMEM_FLOATS (OCEN + 3)
#define SMEM_BYTES  (SMEM_FLOATS * 4)

__global__ void __launch_bounds__(MLP_THREADS, 2)
mlp_kernel(const float* __restrict__ x, const float* __restrict__ xc,
           float* __restrict__ out)
{
    extern __shared__ float sm[];
    const int tid  = threadIdx.x;
    const int tx   = tid & 15;
    const int ty   = tid >> 4;
    const int lane = tid & 31;
    const int warp = tid >> 5;

    for (int i = tid; i < 64*67; i += MLP_THREADS) sm[OW1 + i] = g_wf1[i];
    for (int i = tid; i < 64*64; i += MLP_THREADS) {
        int o = i >> 6, c = i & 63;
        sm[OW2 + o*65 + c] = g_wf2[i];
    }
    for (int i = tid; i < 128*64; i += MLP_THREADS) {
        int o = i >> 6, c = i & 63;
        sm[OW3 + o*65 + c] = g_wf3[i];
    }
    for (int i = tid; i < 64;  i += MLP_THREADS) { sm[OB1+i] = g_bf1[i]; sm[OB2+i] = g_bf2[i]; }
    for (int i = tid; i < 128; i += MLP_THREADS) sm[OB3 + i] = g_bf3[i];

    int* sidx = (int*)&sm[OIDX];
    float* pooled = out + (size_t)Bb * Ss * 3;

    for (int g = 0; g < CPG; g++) {
        const int cen = blockIdx.x * CPG + g;
        const int b = cen >> 11;
        __syncthreads();

        if (tid < Kk) sidx[tid] = g_idx_ball[(size_t)cen * Kk + tid];
        if (tid < 3)  sm[OCEN + tid] = g_cen[cen*3 + tid];
        __syncthreads();

        const float* xcb = xc + (size_t)b * Nn * 64;
        const float* xb  = x  + (size_t)b * Nn * 3;
        for (int kk = 0; kk < 16; kk++) {
            int k  = warp * 16 + kk;
            int gi = sidx[k];
            gi = gi < 0 ? 0 : gi;
            const float* row = xcb + (size_t)gi * 64;
            sm[OF + lane*65 + k]      = row[lane];
            sm[OF + (lane+32)*65 + k] = row[lane + 32];
            if (lane < 3)
                sm[OF + (64+lane)*65 + k] = xb[gi*3 + lane] - sm[OCEN + lane];
        }
        __syncthreads();

        float acc[8][4];

#pragma unroll
        for (int i = 0; i < 8; i++)
#pragma unroll
            for (int j = 0; j < 4; j++) acc[i][j] = 0.f;
        for (int c = 0; c < 67; c++) {
            float fv[4];
#pragma unroll
            for (int j = 0; j < 4; j++) fv[j] = sm[OF + c*65 + tx*4 + j];
#pragma unroll
            for (int i = 0; i < 8; i++) {
                float wv = sm[OW1 + (ty*8 + i)*67 + c];
#pragma unroll
                for (int j = 0; j < 4; j++) acc[i][j] = fmaf(wv, fv[j], acc[i][j]);
            }
        }
#pragma unroll
        for (int i = 0; i < 8; i++) {
            float bia = sm[OB1 + ty*8 + i];
#pragma unroll
            for (int j = 0; j < 4; j++)
                sm[OH + (ty*8 + i)*65 + tx*4 + j] = fmaxf(acc[i][j] + bia, 0.f);
        }
        __syncthreads();

#pragma unroll
        for (int i = 0; i < 8; i++)
#pragma unroll
            for (int j = 0; j < 4; j++) acc[i][j] = 0.f;
        for (int c = 0; c < 64; c++) {
            float fv[4];
#pragma unroll
            for (int j = 0; j < 4; j++) fv[j] = sm[OH + c*65 + tx*4 + j];
#pragma unroll
            for (int i = 0; i < 8; i++) {
                float wv = sm[OW2 + (ty*8 + i)*65 + c];
#pragma unroll
                for (int j = 0; j < 4; j++) acc[i][j] = fmaf(wv, fv[j], acc[i][j]);
            }
        }
#pragma unroll
        for (int i = 0; i < 8; i++) {
            float bia = sm[OB2 + ty*8 + i];
#pragma unroll
            for (int j = 0; j < 4; j++)
                sm[OF + (ty*8 + i)*65 + tx*4 + j] = fmaxf(acc[i][j] + bia, 0.f);
        }
        __syncthreads();

        for (int op = 0; op < 2; op++) {
#pragma unroll
            for (int i = 0; i < 8; i++)
#pragma unroll
                for (int j = 0; j < 4; j++) acc[i][j] = 0.f;
            for (int c = 0; c < 64; c++) {
                float fv[4];
#pragma unroll
                for (int j = 0; j < 4; j++) fv[j] = sm[OF + c*65 + tx*4 + j];
#pragma unroll
                for (int i = 0; i < 8; i++) {
                    float wv = sm[OW3 + (op*64 + ty*8 + i)*65 + c];
#pragma unroll
                    for (int j = 0; j < 4; j++) acc[i][j] = fmaf(wv, fv[j], acc[i][j]);
                }
            }
#pragma unroll
            for (int i = 0; i < 8; i++) {
                int o = op*64 + ty*8 + i;
                float bia = sm[OB3 + o];
                float m = -INFINITY;
#pragma unroll
                for (int j = 0; j < 4; j++) {
                    int k = tx*4 + j;
                    float v = fmaxf(acc[i][j] + bia, 0.f);
                    if (sidx[k] >= 0) m = fmaxf(m, v);
                }
#pragma unroll
                for (int off = 8; off; off >>= 1)
                    m = fmaxf(m, __shfl_xor_sync(0xffffffffu, m, off, 16));
                if (tx == 0) pooled[(size_t)cen * 128 + o] = m;
            }
        }
    }
}

// ---------------- launch ----------------
extern "C" void kernel_launch(void* const* d_in, const int* in_sizes, int n_in,
                              void* d_out, int out_size)
{
    const float* x   = (const float*)d_in[0];
    const float* xc  = (const float*)d_in[1];
    const float* W1  = (const float*)d_in[2];
    const float* b1  = (const float*)d_in[3];
    const float* g1  = (const float*)d_in[4];
    const float* bt1 = (const float*)d_in[5];
    const float* m1  = (const float*)d_in[6];
    const float* v1  = (const float*)d_in[7];
    const float* W2  = (const float*)d_in[8];
    const float* b2  = (const float*)d_in[9];
    const float* g2  = (const float*)d_in[10];
    const float* bt2 = (const float*)d_in[11];
    const float* m2  = (const float*)d_in[12];
    const float* v2  = (const float*)d_in[13];
    const float* W3  = (const float*)d_in[14];
    const float* b3  = (const float*)d_in[15];
    const float* g3  = (const float*)d_in[16];
    const float* bt3 = (const float*)d_in[17];
    const float* m3  = (const float*)d_in[18];
    const float* v3  = (const float*)d_in[19];
    float* out = (float*)d_out;

    fold_kernel<<<1, 256>>>(W1,b1,g1,bt1,m1,v1, W2,b2,g2,bt2,m2,v2, W3,b3,g3,bt3,m3,v3);
    fps_kernel<<<Bb, 1024>>>(x, out);
    ball_kernel<<<(Bb*Ss)/8, 256>>>(x);

    cudaFuncSetAttribute(mlp_kernel, cudaFuncAttributeMaxDynamicSharedMemorySize, SMEM_BYTES);
    mlp_kernel<<<(Bb*Ss)/CPG, MLP_THREADS, SMEM_BYTES>>>(x, xc, out);
}

// round 3
// speedup vs baseline: 1.6213x; 1.1663x over previous
#include <cuda_runtime.h>
#include <math.h>
#include <float.h>

#define Bb 4
#define Nn 8192
#define Ss 2048
#define Kk 64
#define EPSf 1e-5f

#define NCH   16          // FPS chunks
#define CH    128         // steps per chunk (Ss/NCH)
#define WCTAS 128         // worker CTAs per launch
#define TPB   512

typedef unsigned long long ull;

// ---------------- device scratch ----------------
__device__ float g_cen[Bb*Ss*3];
__device__ float g_dist[Bb*Nn];
__device__ int   g_cur[Bb];
__device__ float g_wf1[64*67];
__device__ float g_bf1[64];
__device__ float g_wf2[64*64];
__device__ float g_bf2[64];
__device__ float g_wf3[128*64];
__device__ float g_bf3[128];

// ---------------- packed f32x2 helpers (per-lane rn == scalar rn) ----------------
__device__ __forceinline__ ull pk2(float lo, float hi) {
    ull r; asm("mov.b64 %0, {%1, %2};" : "=l"(r) : "f"(lo), "f"(hi)); return r;
}
__device__ __forceinline__ void up2(ull v, float& a, float& b) {
    asm("mov.b64 {%0, %1}, %2;" : "=f"(a), "=f"(b) : "l"(v));
}
__device__ __forceinline__ ull add2(ull a, ull b) {
    ull r; asm("add.rn.f32x2 %0, %1, %2;" : "=l"(r) : "l"(a), "l"(b)); return r;
}
__device__ __forceinline__ ull mul2(ull a, ull b) {
    ull r; asm("mul.rn.f32x2 %0, %1, %2;" : "=l"(r) : "l"(a), "l"(b)); return r;
}

// ---------------- fold BN into conv + init FPS state ----------------
__global__ void fold_kernel(
    const float* W1, const float* b1, const float* g1, const float* bt1, const float* m1, const float* v1,
    const float* W2, const float* b2, const float* g2, const float* bt2, const float* m2, const float* v2,
    const float* W3, const float* b3, const float* g3, const float* bt3, const float* m3, const float* v3)
{
    int t = threadIdx.x;
    for (int i = t; i < 64*67; i += blockDim.x) {
        int o = i / 67;
        g_wf1[i] = W1[i] * (g1[o] * rsqrtf(v1[o] + EPSf));
    }
    for (int i = t; i < 64; i += blockDim.x)
        g_bf1[i] = (b1[i] - m1[i]) * (g1[i] * rsqrtf(v1[i] + EPSf)) + bt1[i];
    for (int i = t; i < 64*64; i += blockDim.x) {
        int o = i >> 6;
        g_wf2[i] = W2[i] * (g2[o] * rsqrtf(v2[o] + EPSf));
    }
    for (int i = t; i < 64; i += blockDim.x)
        g_bf2[i] = (b2[i] - m2[i]) * (g2[i] * rsqrtf(v2[i] + EPSf)) + bt2[i];
    for (int i = t; i < 128*64; i += blockDim.x) {
        int o = i >> 6;
        g_wf3[i] = W3[i] * (g3[o] * rsqrtf(v3[o] + EPSf));
    }
    for (int i = t; i < 128; i += blockDim.x)
        g_bf3[i] = (b3[i] - m3[i]) * (g3[i] * rsqrtf(v3[i] + EPSf)) + bt3[i];

    // FPS state init (fresh every call)
    for (int i = t; i < Bb*Nn; i += blockDim.x) g_dist[i] = 1e10f;
    if (t < Bb) g_cur[t] = 0;
}

// ---------------- shared-memory layout (floats) ----------------
// worker view
#define OW1 0
#define OB1 (OW1 + 64*67)
#define OW2 (OB1 + 64)
#define OB2 (OW2 + 64*65)
#define OW3 (OB2 + 64)
#define OB3 (OW3 + 128*65)
#define OBUF (OB3 + 128)                 // 17024
#define GRP  (67*65 + 64*65)             // 8515 per warpgroup (F then H)
#define OIDXA (OBUF + 4*GRP)             // 51084
#define SMEM_FLOATS (OIDXA + 4*64)
#define SMEM_BYTES  (SMEM_FLOATS * 4)    // ~205 KB
// fps view (same dynamic buffer, CTAs 0..3 only)
#define FPS_SX 0
#define FPS_SY Nn
#define FPS_SZ (2*Nn)
#define FPS_SVAL (3*Nn)                  // [2][16]
#define FPS_SIDX (3*Nn + 32)             // [2][16]

// =====================================================================
// fused pipeline kernel:
//   CTA 0..3      : FPS chunk fps_chunk (if >=0) for batch = blockIdx.x
//   CTA 4..4+WCTAS: ball query + MLP for centroids of chunk mlp_chunk (if >=0)
// =====================================================================
__global__ void __launch_bounds__(TPB, 1)
pipe_kernel(const float* __restrict__ x, const float* __restrict__ xc,
            float* __restrict__ out, int fps_chunk, int mlp_chunk)
{
    extern __shared__ float sm[];
    const int tid = threadIdx.x;

    if (blockIdx.x < Bb) {
        // ================= FPS =================
        if (fps_chunk < 0) return;
        const int b = blockIdx.x;
        const float* xb = x + (size_t)b * Nn * 3;

        // stage coords into smem (for broadcast centroid reads)
        for (int i = tid; i < Nn; i += TPB) {
            sm[FPS_SX + i] = xb[i*3 + 0];
            sm[FPS_SY + i] = xb[i*3 + 1];
            sm[FPS_SZ + i] = xb[i*3 + 2];
        }

        // 16 points per thread, packed; STATIC indexing only (no spills)
        ull px[8], py[8], pz[8];
        float dist[16];
#pragma unroll
        for (int i = 0; i < 8; i++) {
            int p = tid * 16 + i * 2;
            px[i] = pk2(xb[p*3 + 0], xb[p*3 + 3]);
            py[i] = pk2(xb[p*3 + 1], xb[p*3 + 4]);
            pz[i] = pk2(xb[p*3 + 2], xb[p*3 + 5]);
        }
#pragma unroll
        for (int j = 0; j < 16; j++) dist[j] = g_dist[b*Nn + tid*16 + j];

        int cur = g_cur[b];
        const int lane = tid & 31;
        const int wrp  = tid >> 5;
        __syncthreads();   // coords staged

        const int s0 = fps_chunk * CH;
        for (int si = 0; si < CH; si++) {
            const int s = s0 + si;
            // broadcast centroid read (cur is uniform across block)
            const float cx = sm[FPS_SX + cur];
            const float cy = sm[FPS_SY + cur];
            const float cz = sm[FPS_SZ + cur];
            if (tid == 0) {
                int oc = (b*Ss + s) * 3;
                g_cen[oc+0] = cx; g_cen[oc+1] = cy; g_cen[oc+2] = cz;
                out[oc+0]  = cx; out[oc+1]  = cy; out[oc+2]  = cz;
            }
            const ull ncx = pk2(-cx, -cx);
            const ull ncy = pk2(-cy, -cy);
            const ull ncz = pk2(-cz, -cz);

            float mm[8];
#pragma unroll
            for (int i = 0; i < 8; i++) {
                ull dx = add2(px[i], ncx);
                ull dy = add2(py[i], ncy);
                ull dz = add2(pz[i], ncz);
                ull dd = add2(add2(mul2(dx,dx), mul2(dy,dy)), mul2(dz,dz));
                float d0, d1; up2(dd, d0, d1);
                float n0 = fminf(dist[2*i],   d0);
                float n1 = fminf(dist[2*i+1], d1);
                dist[2*i] = n0; dist[2*i+1] = n1;
                mm[i] = fmaxf(n0, n1);
            }
            float bestv = fmaxf(fmaxf(fmaxf(mm[0],mm[1]), fmaxf(mm[2],mm[3])),
                                fmaxf(fmaxf(mm[4],mm[5]), fmaxf(mm[6],mm[7])));

            // warp argmax: max value (float-as-uint, all >= 0) then min matching index
            unsigned mv   = __float_as_uint(bestv);
            unsigned wmax = __reduce_max_sync(0xffffffffu, mv);
            unsigned loc  = 0xffffffffu;
            if (mv == wmax) {
                float fm = __uint_as_float(wmax);
#pragma unroll
                for (int j = 15; j >= 0; j--)
                    if (dist[j] == fm) loc = (unsigned)(tid*16 + j);  // ends at smallest j
            }
            unsigned widx = __reduce_min_sync(0xffffffffu, loc);

            const int par = si & 1;
            unsigned* sval = (unsigned*)&sm[FPS_SVAL + par*16];
            unsigned* sidx = (unsigned*)&sm[FPS_SIDX + par*16];
            if (lane == 0) { sval[wrp] = wmax; sidx[wrp] = widx; }
            __syncthreads();   // only barrier per step (parity buffers avoid WAR)

            unsigned v  = (lane < 16) ? sval[lane] : 0u;
            unsigned id = (lane < 16) ? sidx[lane] : 0xffffffffu;
            unsigned M  = __reduce_max_sync(0xffffffffu, v);
            unsigned cn = (v == M) ? id : 0xffffffffu;
            cur = (int)__reduce_min_sync(0xffffffffu, cn);
        }

        // persist state
#pragma unroll
        for (int j = 0; j < 16; j++) g_dist[b*Nn + tid*16 + j] = dist[j];
        if (tid == 0) g_cur[b] = cur;
        return;
    }

    // ================= worker: ball query + MLP =================
    if (mlp_chunk < 0) return;
    const int wcta = blockIdx.x - Bb;

    // stage folded weights
    for (int i = tid; i < 64*67; i += TPB) sm[OW1 + i] = g_wf1[i];
    for (int i = tid; i < 64*64; i += TPB) {
        int o = i >> 6, c = i & 63;
        sm[OW2 + o*65 + c] = g_wf2[i];
    }
    for (int i = tid; i < 128*64; i += TPB) {
        int o = i >> 6, c = i & 63;
        sm[OW3 + o*65 + c] = g_wf3[i];
    }
    for (int i = tid; i < 64;  i += TPB) { sm[OB1+i] = g_bf1[i]; sm[OB2+i] = g_bf2[i]; }
    for (int i = tid; i < 128; i += TPB) sm[OB3 + i] = g_bf3[i];

    const int lane = tid & 31;
    const int wrp  = tid >> 5;

    // ---- ball query: warps 0..3, one centroid each (exact r2 math) ----
    if (wrp < 4) {
        const int lin = wcta * 4 + wrp;               // 0..511
        const int b   = lin >> 7;
        const int s   = mlp_chunk * CH + (lin & 127);
        const int cen = b * Ss + s;
        const float cx = g_cen[cen*3 + 0];
        const float cy = g_cen[cen*3 + 1];
        const float cz = g_cen[cen*3 + 2];
        const float* xb = x + (size_t)b * Nn * 3;
        int* outp = (int*)&sm[OIDXA + wrp*64];

        int count = 0;
        for (int base = 0; base < Nn && count < Kk; base += 32) {
            int p = base + lane;
            float qx = xb[p*3 + 0], qy = xb[p*3 + 1], qz = xb[p*3 + 2];
            float dx = __fsub_rn(cx, qx);
            float dy = __fsub_rn(cy, qy);
            float dz = __fsub_rn(cz, qz);
            float d  = __fadd_rn(__fadd_rn(__fmul_rn(dx,dx), __fmul_rn(dy,dy)),
                                 __fmul_rn(dz,dz));
            bool hit = d < 0.04f;
            unsigned m = __ballot_sync(0xffffffffu, hit);
            int rank = __popc(m & ((1u << lane) - 1u));
            if (hit && (count + rank) < Kk) outp[count + rank] = p;
            count += __popc(m);
        }
        count = min(count, Kk);
        for (int q = count + lane; q < Kk; q += 32) outp[q] = -1;
    }
    __syncthreads();  // weights + ball idx ready

    // ---- MLP: 4 warpgroups, one centroid each (exact r2 math) ----
    const int wgid   = tid >> 7;        // 0..3
    const int wg_tid = tid & 127;
    const int tx = wg_tid & 15;
    const int ty = wg_tid >> 4;
    const int wg_warp = (tid >> 5) & 3;

    const int lin = wcta * 4 + wgid;
    const int b   = lin >> 7;
    const int cen = b * Ss + mlp_chunk * CH + (lin & 127);

    const int OF = OBUF + wgid * GRP;   // F [67][65]
    const int OH = OF + 67*65;          // H [64][65]
    int* sidx = (int*)&sm[OIDXA + wgid*64];
    float* pooled = out + (size_t)Bb * Ss * 3;

    // gather: F[c][k]
    const float* xcb = xc + (size_t)b * Nn * 64;
    const float* xb  = x  + (size_t)b * Nn * 3;
    for (int kk = 0; kk < 16; kk++) {
        int k  = wg_warp * 16 + kk;
        int gi = sidx[k];
        gi = gi < 0 ? 0 : gi;
        const float* row = xcb + (size_t)gi * 64;
        sm[OF + lane*65 + k]      = row[lane];
        sm[OF + (lane+32)*65 + k] = row[lane + 32];
        if (lane < 3)
            sm[OF + (64+lane)*65 + k] = xb[gi*3 + lane] - g_cen[cen*3 + lane];
    }
    __syncthreads();

    float acc[8][4];

    // layer 1
#pragma unroll
    for (int i = 0; i < 8; i++)
#pragma unroll
        for (int j = 0; j < 4; j++) acc[i][j] = 0.f;
    for (int c = 0; c < 67; c++) {
        float fv[4];
#pragma unroll
        for (int j = 0; j < 4; j++) fv[j] = sm[OF + c*65 + tx*4 + j];
#pragma unroll
        for (int i = 0; i < 8; i++) {
            float wv = sm[OW1 + (ty*8 + i)*67 + c];
#pragma unroll
            for (int j = 0; j < 4; j++) acc[i][j] = fmaf(wv, fv[j], acc[i][j]);
        }
    }
#pragma unroll
    for (int i = 0; i < 8; i++) {
        float bia = sm[OB1 + ty*8 + i];
#pragma unroll
        for (int j = 0; j < 4; j++)
            sm[OH + (ty*8 + i)*65 + tx*4 + j] = fmaxf(acc[i][j] + bia, 0.f);
    }
    __syncthreads();

    // layer 2 (into F buffer)
#pragma unroll
    for (int i = 0; i < 8; i++)
#pragma unroll
        for (int j = 0; j < 4; j++) acc[i][j] = 0.f;
    for (int c = 0; c < 64; c++) {
        float fv[4];
#pragma unroll
        for (int j = 0; j < 4; j++) fv[j] = sm[OH + c*65 + tx*4 + j];
#pragma unroll
        for (int i = 0; i < 8; i++) {
            float wv = sm[OW2 + (ty*8 + i)*65 + c];
#pragma unroll
            for (int j = 0; j < 4; j++) acc[i][j] = fmaf(wv, fv[j], acc[i][j]);
        }
    }
#pragma unroll
    for (int i = 0; i < 8; i++) {
        float bia = sm[OB2 + ty*8 + i];
#pragma unroll
        for (int j = 0; j < 4; j++)
            sm[OF + (ty*8 + i)*65 + tx*4 + j] = fmaxf(acc[i][j] + bia, 0.f);
    }
    __syncthreads();

    // layer 3 + masked maxpool
    for (int op = 0; op < 2; op++) {
#pragma unroll
        for (int i = 0; i < 8; i++)
#pragma unroll
            for (int j = 0; j < 4; j++) acc[i][j] = 0.f;
        for (int c = 0; c < 64; c++) {
            float fv[4];
#pragma unroll
            for (int j = 0; j < 4; j++) fv[j] = sm[OF + c*65 + tx*4 + j];
#pragma unroll
            for (int i = 0; i < 8; i++) {
                float wv = sm[OW3 + (op*64 + ty*8 + i)*65 + c];
#pragma unroll
                for (int j = 0; j < 4; j++) acc[i][j] = fmaf(wv, fv[j], acc[i][j]);
            }
        }
#pragma unroll
        for (int i = 0; i < 8; i++) {
            int o = op*64 + ty*8 + i;
            float bia = sm[OB3 + o];
            float m = -INFINITY;
#pragma unroll
            for (int j = 0; j < 4; j++) {
                int k = tx*4 + j;
                float v = fmaxf(acc[i][j] + bia, 0.f);
                if (sidx[k] >= 0) m = fmaxf(m, v);
            }
#pragma unroll
            for (int off = 8; off; off >>= 1)
                m = fmaxf(m, __shfl_xor_sync(0xffffffffu, m, off, 16));
            if (tx == 0) pooled[(size_t)cen * 128 + o] = m;
        }
    }
}

// ---------------- launch ----------------
extern "C" void kernel_launch(void* const* d_in, const int* in_sizes, int n_in,
                              void* d_out, int out_size)
{
    const float* x   = (const float*)d_in[0];
    const float* xc  = (const float*)d_in[1];
    const float* W1  = (const float*)d_in[2];
    const float* b1  = (const float*)d_in[3];
    const float* g1  = (const float*)d_in[4];
    const float* bt1 = (const float*)d_in[5];
    const float* m1  = (const float*)d_in[6];
    const float* v1  = (const float*)d_in[7];
    const float* W2  = (const float*)d_in[8];
    const float* b2  = (const float*)d_in[9];
    const float* g2  = (const float*)d_in[10];
    const float* bt2 = (const float*)d_in[11];
    const float* m2  = (const float*)d_in[12];
    const float* v2  = (const float*)d_in[13];
    const float* W3  = (const float*)d_in[14];
    const float* b3  = (const float*)d_in[15];
    const float* g3  = (const float*)d_in[16];
    const float* bt3 = (const float*)d_in[17];
    const float* m3  = (const float*)d_in[18];
    const float* v3  = (const float*)d_in[19];
    float* out = (float*)d_out;

    fold_kernel<<<1, 256>>>(W1,b1,g1,bt1,m1,v1, W2,b2,g2,bt2,m2,v2, W3,b3,g3,bt3,m3,v3);

    cudaFuncSetAttribute(pipe_kernel, cudaFuncAttributeMaxDynamicSharedMemorySize, SMEM_BYTES);
    const int grid = Bb + WCTAS;

    // software pipeline: FPS chunk c  ||  ball+MLP for chunk c-1
    pipe_kernel<<<grid, TPB, SMEM_BYTES>>>(x, xc, out, 0, -1);
    for (int c = 1; c < NCH; c++)
        pipe_kernel<<<grid, TPB, SMEM_BYTES>>>(x, xc, out, c, c - 1);
    pipe_kernel<<<grid, TPB, SMEM_BYTES>>>(x, xc, out, -1, NCH - 1);
}